// round 10
// baseline (speedup 1.0000x reference)
#include <cuda_runtime.h>
#include <cuda_bf16.h>
#include <math.h>
#include <stdint.h>

#define B_  256
#define T_  512
#define D_  128
#define H_  256
#define G_  768
#define C_  10

// ---------------- warp-mma / cluster helpers (baseline PTX, plain sm_103) ---------
__device__ __forceinline__ uint32_t smem_u32(const void* p) {
    uint32_t a;
    asm("{ .reg .u64 t; cvta.to.shared.u64 t, %1; cvt.u32.u64 %0, t; }" : "=r"(a) : "l"(p));
    return a;
}
__device__ __forceinline__ uint32_t mapa_u32(uint32_t a, uint32_t rank) {
    uint32_t d;
    asm("mapa.shared::cluster.u32 %0, %1, %2;" : "=r"(d) : "r"(a), "r"(rank));
    return d;
}
#define LDSM4(r0, r1, r2, r3, addr) \
    asm volatile("ldmatrix.sync.aligned.m8n8.x4.shared.b16 {%0,%1,%2,%3}, [%4];" \
        : "=r"(r0), "=r"(r1), "=r"(r2), "=r"(r3) : "r"(addr))
#define LDSM2(r0, r1, addr) \
    asm volatile("ldmatrix.sync.aligned.m8n8.x2.shared.b16 {%0,%1}, [%2];" \
        : "=r"(r0), "=r"(r1) : "r"(addr))
#define MMA16816(c, a, b0v, b1v) \
    asm volatile("mma.sync.aligned.m16n8k16.row.col.f32.bf16.bf16.f32 " \
        "{%0,%1,%2,%3},{%4,%5,%6,%7},{%8,%9},{%0,%1,%2,%3};" \
        : "+f"((c)[0]), "+f"((c)[1]), "+f"((c)[2]), "+f"((c)[3]) \
        : "r"((a)[0]), "r"((a)[1]), "r"((a)[2]), "r"((a)[3]), "r"(b0v), "r"(b1v))
#define STSC4(addr, u) \
    asm volatile("st.shared::cluster.v4.u32 [%0], {%1,%2,%3,%4};" \
        :: "r"(addr), "r"((u).x), "r"((u).y), "r"((u).z), "r"((u).w) : "memory")
#define CLUSTER_SYNC() do { \
    asm volatile("barrier.cluster.arrive.aligned;" ::: "memory"); \
    asm volatile("barrier.cluster.wait.aligned;" ::: "memory"); \
} while (0)

// ---------------- scratch (device globals; no allocation allowed) ----------------
__device__ float g_gi[(size_t)B_ * T_ * G_];            // gi for current layer
__device__ __nv_bfloat16 g_seqhi[(size_t)T_ * B_ * H_]; // layer-0 h sequence, bf16 hi
__device__ __nv_bfloat16 g_seqlo[(size_t)T_ * B_ * H_]; // layer-0 h sequence, bf16 lo
__device__ float g_hlast[B_ * H_];                      // final fp32 h for the FC
__device__ __nv_bfloat16 g_ahi[(size_t)131072 * 128];   // x split (layer-0 gi GEMM)
__device__ __nv_bfloat16 g_alo[(size_t)131072 * 128];
__device__ __nv_bfloat16 g_whi[G_ * H_];
__device__ __nv_bfloat16 g_wlo[G_ * H_];

// ---------------- fp32 -> (bf16 hi, bf16 lo) split ---------------------------------
__global__ void split_bf16(const float* __restrict__ s, __nv_bfloat16* __restrict__ hi,
                           __nv_bfloat16* __restrict__ lo, int n4)
{
    const int i = blockIdx.x * blockDim.x + threadIdx.x;
    if (i >= n4) return;
    const float4 v = ((const float4*)s)[i];
    __nv_bfloat16 h0 = __float2bfloat16(v.x);
    __nv_bfloat16 h1 = __float2bfloat16(v.y);
    __nv_bfloat16 h2 = __float2bfloat16(v.z);
    __nv_bfloat16 h3 = __float2bfloat16(v.w);
    __nv_bfloat16 l0 = __float2bfloat16(v.x - __bfloat162float(h0));
    __nv_bfloat16 l1 = __float2bfloat16(v.y - __bfloat162float(h1));
    __nv_bfloat16 l2 = __float2bfloat16(v.z - __bfloat162float(h2));
    __nv_bfloat16 l3 = __float2bfloat16(v.w - __bfloat162float(h3));
    __nv_bfloat162* hp = (__nv_bfloat162*)hi;
    __nv_bfloat162* lp = (__nv_bfloat162*)lo;
    hp[i * 2 + 0] = __nv_bfloat162(h0, h1);
    hp[i * 2 + 1] = __nv_bfloat162(h2, h3);
    lp[i * 2 + 0] = __nv_bfloat162(l0, l1);
    lp[i * 2 + 1] = __nv_bfloat162(l2, l3);
}

// ---------------- split-bf16 HMMA GEMM (R8/R9-proven, unchanged) -------------------
__global__ void __launch_bounds__(256, 1) mma_gemm(
    const __nv_bfloat16* __restrict__ Ahi, const __nv_bfloat16* __restrict__ Alo,
    const __nv_bfloat16* __restrict__ Whi, const __nv_bfloat16* __restrict__ Wlo,
    const float* __restrict__ bias, float* __restrict__ C, int K)
{
    extern __shared__ char smem[];
    const int KS = K + 8;
    const int strB = KS * 2;
    char* sAhi = smem;
    char* sAlo = sAhi + 128 * strB;
    char* sWhi = sAlo + 128 * strB;
    char* sWlo = sWhi + 64 * strB;

    const int tid = threadIdx.x;
    const int n0 = blockIdx.x * 64;
    const int m0 = blockIdx.y * 128;

    const int cpr = K >> 3;
    for (int c = tid; c < 128 * cpr; c += 256) {
        const int r = c / cpr, kc = c % cpr;
        const size_t src = (size_t)(m0 + r) * K + kc * 8;
        *(uint4*)(sAhi + r * strB + kc * 16) = *(const uint4*)(Ahi + src);
        *(uint4*)(sAlo + r * strB + kc * 16) = *(const uint4*)(Alo + src);
    }
    for (int c = tid; c < 64 * cpr; c += 256) {
        const int r = c / cpr, kc = c % cpr;
        const size_t src = (size_t)(n0 + r) * K + kc * 8;
        *(uint4*)(sWhi + r * strB + kc * 16) = *(const uint4*)(Whi + src);
        *(uint4*)(sWlo + r * strB + kc * 16) = *(const uint4*)(Wlo + src);
    }
    __syncthreads();

    const int wid = tid >> 5, lane = tid & 31;
    const int mw = wid >> 1, nw = wid & 1;

    float acc[2][4][4];
#pragma unroll
    for (int mt = 0; mt < 2; mt++)
#pragma unroll
        for (int nt = 0; nt < 4; nt++)
#pragma unroll
            for (int q = 0; q < 4; q++) acc[mt][nt][q] = 0.f;

    const int aRow = mw * 32 + (lane & 15);
    const int aKof = (lane >> 4) * 16;
    const int bRow = nw * 32 + (lane & 7) + ((lane >> 4) << 3);
    const int bKof = ((lane >> 3) & 1) * 16;

    const uint32_t uAhi = smem_u32(sAhi), uAlo = smem_u32(sAlo);
    const uint32_t uWhi = smem_u32(sWhi), uWlo = smem_u32(sWlo);

    const int nks = K >> 4;
    for (int ks = 0; ks < nks; ks++) {
        const int kb = ks * 32;
        uint32_t ah[2][4], al[2][4], bh[4][2], bl[4][2];
#pragma unroll
        for (int mt = 0; mt < 2; mt++) {
            const uint32_t ra = (uint32_t)((aRow + mt * 16) * strB + kb + aKof);
            LDSM4(ah[mt][0], ah[mt][1], ah[mt][2], ah[mt][3], uAhi + ra);
            LDSM4(al[mt][0], al[mt][1], al[mt][2], al[mt][3], uAlo + ra);
        }
#pragma unroll
        for (int np = 0; np < 2; np++) {
            const uint32_t rb = (uint32_t)((bRow + np * 16) * strB + kb + bKof);
            uint32_t t0, t1, t2, t3;
            LDSM4(t0, t1, t2, t3, uWhi + rb);
            bh[np * 2][0] = t0; bh[np * 2][1] = t1;
            bh[np * 2 + 1][0] = t2; bh[np * 2 + 1][1] = t3;
            LDSM4(t0, t1, t2, t3, uWlo + rb);
            bl[np * 2][0] = t0; bl[np * 2][1] = t1;
            bl[np * 2 + 1][0] = t2; bl[np * 2 + 1][1] = t3;
        }
#pragma unroll
        for (int mt = 0; mt < 2; mt++)
#pragma unroll
            for (int nt = 0; nt < 4; nt++) {
                MMA16816(acc[mt][nt], ah[mt], bh[nt][0], bh[nt][1]);
                MMA16816(acc[mt][nt], ah[mt], bl[nt][0], bl[nt][1]);
                MMA16816(acc[mt][nt], al[mt], bh[nt][0], bh[nt][1]);
            }
    }

#pragma unroll
    for (int mt = 0; mt < 2; mt++)
#pragma unroll
        for (int nt = 0; nt < 4; nt++) {
            const int row = m0 + mw * 32 + mt * 16 + (lane >> 2);
            const int col = n0 + nw * 32 + nt * 8 + (lane & 3) * 2;
            const float b0 = bias[col], b1 = bias[col + 1];
            float2 o0, o1;
            o0.x = acc[mt][nt][0] + b0; o0.y = acc[mt][nt][1] + b1;
            o1.x = acc[mt][nt][2] + b0; o1.y = acc[mt][nt][3] + b1;
            *(float2*)&C[(size_t)row * G_ + col]       = o0;
            *(float2*)&C[(size_t)(row + 8) * G_ + col] = o1;
        }
}

// ---------------- clustered GRU scan: DSMEM h exchange -----------------------------
// 16 clusters x 8 CTAs x 256 threads. Cluster = one 16-batch group (self-contained).
// CTA rank r owns hidden dims [r*32, r*32+32). Whh slice 96x256 hi/lo in smem.
// Per-step: HMMA GEMM (8 warps = 4 n-groups x 2 K-halves) -> gates -> h_new pushed
// into all 8 peers' staging smem via st.shared::cluster -> cluster.sync. No global
// barrier, no global h traffic.
// smem byte map (total 163264):
//   0      swhi [96][528]        50688
//   50688  swlo [96][528]        50688
//   101376 hs [2 buf][hi/lo][16][528]   2*16896
//   135168 part [2][16][100] f32 12800
//   147968 gis [2][1600] f32     12800
//   160768 hst [16][33] f32      2112
//   162880 bsl [96] f32          384
__global__ void __launch_bounds__(256, 1) __cluster_dims__(8, 1, 1)
gru_scan_cl(const float* __restrict__ gi, const float* __restrict__ Whh,
            const float* __restrict__ bhh,
            __nv_bfloat16* __restrict__ seqhi, __nv_bfloat16* __restrict__ seqlo,
            int tmajor)
{
    extern __shared__ char smc[];
    const uint32_t sbase = smem_u32(smc);
    __nv_bfloat16* swhi = (__nv_bfloat16*)smc;
    __nv_bfloat16* swlo = (__nv_bfloat16*)(smc + 50688);
    float* part = (float*)(smc + 135168);
    float* gis  = (float*)(smc + 147968);
    float* hst  = (float*)(smc + 160768);
    float* bsl  = (float*)(smc + 162880);

    const int tid  = threadIdx.x;
    const int cta  = blockIdx.x;
    const int bblk = cta >> 3;
    const int rank = cta & 7;            // cluster_ctarank
    const int b0   = bblk * 16;
    const int j0   = rank * 32;

    // ---- persistent Whh slice (rows gate*32+jj -> Whh[gate*H + j0+jj]), hi/lo ----
    for (int idx = tid; idx < 96 * 256; idx += 256) {
        const int rr = idx >> 8, k = idx & 255;
        const float v = Whh[(size_t)((rr >> 5) * H_ + j0 + (rr & 31)) * H_ + k];
        const __nv_bfloat16 hi = __float2bfloat16(v);
        swhi[rr * 264 + k] = hi;
        swlo[rr * 264 + k] = __float2bfloat16(v - __bfloat162float(hi));
    }
    if (tid < 96) bsl[tid] = bhh[(tid >> 5) * H_ + j0 + (tid & 31)];
    // zero fp32 h_old and hs buffer 0 (hi+lo)
    for (int idx = tid; idx < 16 * 33; idx += 256) hst[idx] = 0.f;
    {
        const uint4 z4 = make_uint4(0u, 0u, 0u, 0u);
#pragma unroll
        for (int q = 0; q < 4; q++) {
            const int v = tid + 256 * q;     // 1024 uint4 = 16KB (hi+lo blocks)
            const int blkrow = v >> 5, c = v & 31;
            if (blkrow < 32)
                *(uint4*)(smc + 101376 + blkrow * 528 + c * 16) = z4;
        }
    }

    const int w = tid >> 5, lane = tid & 31;
    const int nw = w & 3, kh = w >> 2;

    // ldmatrix lane addressing (R8-validated pattern; 1 m16 tile, n-group base nw*24)
    const int aoff   = (lane & 15) * 528 + (lane >> 4) * 16;
    const int boff01 = (nw * 24 + (lane & 7) + ((lane >> 4) << 3)) * 528
                     + ((lane >> 3) & 1) * 16;
    const int boff2  = (nw * 24 + 16 + (lane & 7)) * 528 + ((lane >> 3) & 1) * 16;
    const uint32_t uWhi = sbase, uWlo = sbase + 50688;

    // per-thread gi staging map (6 elements: 16 b x 96 cols)
    int gq_b[6], gq_sm[6], gq_col[6];
#pragma unroll
    for (int q = 0; q < 6; q++) {
        const int idx = tid + 256 * q;
        const int b = idx / 96, gg = idx % 96;
        gq_b[q] = b;
        gq_sm[q] = b * 100 + gg;
        gq_col[q] = (gg >> 5) * H_ + j0 + (gg & 31);
    }
    float greg[6];
#pragma unroll
    for (int q = 0; q < 6; q++) {
        const size_t row = tmajor ? ((size_t)0 * B_ + b0 + gq_b[q])
                                  : ((size_t)(b0 + gq_b[q]) * T_ + 0);
        greg[q] = gi[row * G_ + gq_col[q]];
    }
#pragma unroll
    for (int q = 0; q < 6; q++) gis[gq_sm[q]] = greg[q];
    __syncthreads();

    for (int t = 0; t < T_; t++) {
        const int cur = t & 1, nxt = cur ^ 1;
        const float* gcur = gis + cur * 1600;
        float* gnxt = gis + nxt * 1600;
        const uint32_t uhs = sbase + 101376 + cur * 16896;   // hi block; lo at +8448

        // ---- prefetch gi(t+1) (hidden under GEMM) ----
        {
            const int tn = (t + 1 < T_) ? (t + 1) : t;
#pragma unroll
            for (int q = 0; q < 6; q++) {
                const size_t row = tmajor ? ((size_t)tn * B_ + b0 + gq_b[q])
                                          : ((size_t)(b0 + gq_b[q]) * T_ + tn);
                greg[q] = __ldg(&gi[row * G_ + gq_col[q]]);
            }
        }

        // ---- HMMA GEMM: gh[16][96], K-half kh, n-group nw, 3 split passes ----
        float a0[4] = {0.f, 0.f, 0.f, 0.f};
        float a1[4] = {0.f, 0.f, 0.f, 0.f};
        float a2[4] = {0.f, 0.f, 0.f, 0.f};
#pragma unroll
        for (int ks = 0; ks < 8; ks++) {
            const int kb = kh * 256 + ks * 32;
            uint32_t ah[4], al[4], bh01[4], bl01[4], bh2[2], bl2[2];
            LDSM4(ah[0], ah[1], ah[2], ah[3], uhs + aoff + kb);
            LDSM4(al[0], al[1], al[2], al[3], uhs + 8448 + aoff + kb);
            LDSM4(bh01[0], bh01[1], bh01[2], bh01[3], uWhi + boff01 + kb);
            LDSM2(bh2[0], bh2[1], uWhi + boff2 + kb);
            LDSM4(bl01[0], bl01[1], bl01[2], bl01[3], uWlo + boff01 + kb);
            LDSM2(bl2[0], bl2[1], uWlo + boff2 + kb);
            MMA16816(a0, ah, bh01[0], bh01[1]);
            MMA16816(a1, ah, bh01[2], bh01[3]);
            MMA16816(a2, ah, bh2[0], bh2[1]);
            MMA16816(a0, ah, bl01[0], bl01[1]);
            MMA16816(a1, ah, bl01[2], bl01[3]);
            MMA16816(a2, ah, bl2[0], bl2[1]);
            MMA16816(a0, al, bh01[0], bh01[1]);
            MMA16816(a1, al, bh01[2], bh01[3]);
            MMA16816(a2, al, bh2[0], bh2[1]);
        }
        // fragment store: row = lane>>2 {+8}, col = nw*24 + {0,8,16}*tile + 2*(lane&3)
        {
            float* p = &part[kh * 1600 + (lane >> 2) * 100 + nw * 24];
            const int c2 = 2 * (lane & 3);
            p[c2] = a0[0];       p[c2 + 1] = a0[1];
            p[8 + c2] = a1[0];   p[9 + c2] = a1[1];
            p[16 + c2] = a2[0];  p[17 + c2] = a2[1];
            float* p8 = p + 8 * 100;
            p8[c2] = a0[2];      p8[c2 + 1] = a0[3];
            p8[8 + c2] = a1[2];  p8[9 + c2] = a1[3];
            p8[16 + c2] = a2[2]; p8[17 + c2] = a2[3];
        }
#pragma unroll
        for (int q = 0; q < 6; q++) gnxt[gq_sm[q]] = greg[q];
        __syncthreads();

        // ---- gates: 2 (b,jj) per thread; exclusive hst ownership ----
#pragma unroll
        for (int p = 0; p < 2; p++) {
            const int pr = tid + p * 256;
            const int b = pr >> 5, jj = pr & 31;
            const float* p0 = &part[b * 100];
            const float* p1 = &part[1600 + b * 100];
            const float* gc = &gcur[b * 100];
            const float sr = bsl[jj] + p0[jj] + p1[jj] + gc[jj];
            const float sz = bsl[32 + jj] + p0[32 + jj] + p1[32 + jj] + gc[32 + jj];
            const float sn = bsl[64 + jj] + p0[64 + jj] + p1[64 + jj];
            const float r = __fdividef(1.f, 1.f + __expf(-sr));
            const float z = __fdividef(1.f, 1.f + __expf(-sz));
            const float a = gc[64 + jj] + r * sn;
            const float n = __fdividef(2.f, 1.f + __expf(-2.f * a)) - 1.f;
            const float hold = hst[b * 33 + jj];
            hst[b * 33 + jj] = (1.f - z) * n + z * hold;
        }
        __syncthreads();

        // ---- convert h_new slice to hi/lo, push to all 8 cluster CTAs ----
        if (tid < 128) {
            const int half = tid >> 6;          // 0 = hi, 1 = lo
            const int q = tid & 63;
            const int b = q >> 2, seg = q & 3;  // 8 values per task
            float f[8];
            union { __nv_bfloat16 a8[8]; uint4 u; } u;
#pragma unroll
            for (int j = 0; j < 8; j++) {
                f[j] = hst[b * 33 + seg * 8 + j];
                const __nv_bfloat16 hi = __float2bfloat16(f[j]);
                u.a8[j] = half ? __float2bfloat16(f[j] - __bfloat162float(hi)) : hi;
            }
            const uint32_t loff = 101376 + nxt * 16896 + half * 8448
                                + b * 528 + rank * 64 + seg * 16;
#pragma unroll
            for (int r = 0; r < 8; r++) {
                const uint32_t ra = mapa_u32(sbase + loff, (uint32_t)r);
                STSC4(ra, u.u);
            }
            if (seqhi) {
                __nv_bfloat16* sq = half ? seqlo : seqhi;
                const size_t so = ((size_t)t * B_ + b0 + b) * H_ + j0 + seg * 8;
                *(uint4*)&sq[so] = u.u;
            }
            if (t == T_ - 1 && half == 0) {
                const size_t go = (size_t)(b0 + b) * H_ + j0 + seg * 8;
                *(float4*)&g_hlast[go]     = make_float4(f[0], f[1], f[2], f[3]);
                *(float4*)&g_hlast[go + 4] = make_float4(f[4], f[5], f[6], f[7]);
            }
        }

        // ---- one cluster barrier per step (DSMEM visibility + phase flip) ----
        CLUSTER_SYNC();
    }
}

// ---------------- final FC: out[256,10] = h @ Wfc^T + bfc -------------------------
__global__ void fc_kernel(const float* __restrict__ h, const float* __restrict__ Wfc,
                          const float* __restrict__ bfc, float* __restrict__ out)
{
    const int b = blockIdx.x;
    const int lane = threadIdx.x;
    float hv[8];
#pragma unroll
    for (int i = 0; i < 8; i++) hv[i] = h[b * H_ + lane + 32 * i];
    for (int cc = 0; cc < C_; cc++) {
        float s = 0.f;
#pragma unroll
        for (int i = 0; i < 8; i++) s += hv[i] * Wfc[cc * H_ + lane + 32 * i];
#pragma unroll
        for (int o = 16; o > 0; o >>= 1) s += __shfl_down_sync(0xffffffffu, s, o);
        if (lane == 0) out[b * C_ + cc] = s + bfc[cc];
    }
}

// ---------------- launch ----------------------------------------------------------
extern "C" void kernel_launch(void* const* d_in, const int* in_sizes, int n_in,
                              void* d_out, int out_size)
{
    (void)in_sizes; (void)n_in; (void)out_size;
    const float* x    = (const float*)d_in[0];
    const float* Wih0 = (const float*)d_in[1];
    const float* Whh0 = (const float*)d_in[2];
    const float* bih0 = (const float*)d_in[3];
    const float* bhh0 = (const float*)d_in[4];
    const float* Wih1 = (const float*)d_in[5];
    const float* Whh1 = (const float*)d_in[6];
    const float* bih1 = (const float*)d_in[7];
    const float* bhh1 = (const float*)d_in[8];
    const float* Wfc  = (const float*)d_in[9];
    const float* bfc  = (const float*)d_in[10];
    float* out = (float*)d_out;

    float *p_gi, *p_hl;
    __nv_bfloat16 *p_ahi, *p_alo, *p_whi, *p_wlo, *p_shi, *p_slo;
    cudaGetSymbolAddress((void**)&p_gi, g_gi);
    cudaGetSymbolAddress((void**)&p_hl, g_hlast);
    cudaGetSymbolAddress((void**)&p_ahi, g_ahi);
    cudaGetSymbolAddress((void**)&p_alo, g_alo);
    cudaGetSymbolAddress((void**)&p_whi, g_whi);
    cudaGetSymbolAddress((void**)&p_wlo, g_wlo);
    cudaGetSymbolAddress((void**)&p_shi, g_seqhi);
    cudaGetSymbolAddress((void**)&p_slo, g_seqlo);

    const int scan_smem = 163264;
    cudaFuncSetAttribute(gru_scan_cl, cudaFuncAttributeMaxDynamicSharedMemorySize, scan_smem);
    const int gemm_smem1 = 384 * (256 + 8) * 2;
    const int gemm_smem0 = 384 * (128 + 8) * 2;
    cudaFuncSetAttribute(mma_gemm, cudaFuncAttributeMaxDynamicSharedMemorySize, gemm_smem1);

    const dim3 gtile(12, 1024);

    // ---- layer 0: gi0 = x @ Wih0^T + bih0 (rows b*T+t) ----
    split_bf16<<<(131072 * 128 / 4 + 255) / 256, 256>>>(x, p_ahi, p_alo, 131072 * 128 / 4);
    split_bf16<<<(G_ * D_ / 4 + 255) / 256, 256>>>(Wih0, p_whi, p_wlo, G_ * D_ / 4);
    mma_gemm<<<gtile, 256, gemm_smem0>>>(p_ahi, p_alo, p_whi, p_wlo, bih0, p_gi, D_);
    gru_scan_cl<<<128, 256, scan_smem>>>(p_gi, Whh0, bhh0, p_shi, p_slo, /*tmajor=*/0);

    // ---- layer 1: gi1 = h1 @ Wih1^T + bih1 (rows t*B+b, hi/lo straight from scan) ----
    split_bf16<<<(G_ * H_ / 4 + 255) / 256, 256>>>(Wih1, p_whi, p_wlo, G_ * H_ / 4);
    mma_gemm<<<gtile, 256, gemm_smem1>>>(p_shi, p_slo, p_whi, p_wlo, bih1, p_gi, H_);
    gru_scan_cl<<<128, 256, scan_smem>>>(p_gi, Whh1, bhh1, nullptr, nullptr, /*tmajor=*/1);

    // classifier on final hidden state
    fc_kernel<<<B_, 32>>>(p_hl, Wfc, bfc, out);
}